// round 16
// baseline (speedup 1.0000x reference)
#include <cuda_runtime.h>
#include <cuda_bf16.h>
#include <cstdint>

#define NS     16
#define NC     256
#define D      64
#define NPTS   32768
#define NITER  5
#define TILE_M 128
#define NTILE  (NPTS / TILE_M)   // 256 tiles per space
#define CAP    16
#define MARGIN 0.5f

// ---------------- scratch ----------------
__device__ float          g_c[2][NS * NC * D];
__device__ __nv_bfloat16  g_xb[NS * NPTS * D];      // bf16(x)
__device__ __nv_bfloat16  g_ch[NS * NC * D];        // c hi split
__device__ __nv_bfloat16  g_cl[NS * NC * D];        // c lo split
__device__ float          g_c2[NS * NC];
__device__ unsigned char  g_assign[NS * NPTS];
__device__ unsigned short g_bucket[NS * NPTS];
__device__ int            g_cnt[NS * NC];
__device__ int            g_off[NS * NC];
__device__ __align__(16) int g_bh[NS * NC * NTILE];     // [s][k][tile]
__device__ __align__(16) int g_bhoff[NS * NC * NTILE];  // [s][k][tile]

#define SW128(off) ((off) ^ (((off) >> 3) & 0x70))

__device__ __forceinline__ uint32_t smem_u32(const void* p) {
    uint32_t a;
    asm("{ .reg .u64 t; cvta.to.shared.u64 t, %1; cvt.u32.u64 %0, t; }"
        : "=r"(a) : "l"(p));
    return a;
}

#define LDSM_X4(r0, r1, r2, r3, addr) \
    asm volatile("ldmatrix.sync.aligned.m8n8.x4.shared.b16 {%0,%1,%2,%3}, [%4];" \
        : "=r"(r0), "=r"(r1), "=r"(r2), "=r"(r3) : "r"(addr))

#define CP16(dst, src) \
    asm volatile("cp.async.cg.shared.global [%0], [%1], 16;" :: "r"(dst), "l"(src))
#define CP_COMMIT() asm volatile("cp.async.commit_group;")
#define CP_WAIT(n)  asm volatile("cp.async.wait_group %0;" :: "n"(n))

__device__ __forceinline__ void mma16816(float* c, const uint32_t* a,
                                         uint32_t b0, uint32_t b1) {
    asm("mma.sync.aligned.m16n8k16.row.col.f32.bf16.bf16.f32 "
        "{%0,%1,%2,%3}, {%4,%5,%6,%7}, {%8,%9}, {%0,%1,%2,%3};"
        : "+f"(c[0]), "+f"(c[1]), "+f"(c[2]), "+f"(c[3])
        : "r"(a[0]), "r"(a[1]), "r"(a[2]), "r"(a[3]), "r"(b0), "r"(b1));
}

// monotone float <-> ordered-uint
__device__ __forceinline__ uint32_t ford(float f) {
    uint32_t u = __float_as_uint(f);
    return u ^ (uint32_t)(((int32_t)u >> 31) | 0x80000000);
}
__device__ __forceinline__ float funord(uint32_t u) {
    uint32_t v = (u & 0x80000000u) ? (u ^ 0x80000000u) : ~u;
    return __uint_as_float(v);
}

// ---------------- init ----------------
__global__ void init_c_kernel(const float* __restrict__ x) {
    int gid = blockIdx.x * blockDim.x + threadIdx.x;
    int d = gid & 63;
    int k = (gid >> 6) & 255;
    int s = gid >> 14;
    g_c[0][gid] = x[((size_t)k * NS + s) * D + d];
}

__global__ void init_xb_kernel(const float* __restrict__ x) {
    int gid = blockIdx.x * blockDim.x + threadIdx.x;
    int d = gid & 63;
    int n = (gid >> 6) & (NPTS - 1);
    int s = gid >> 21;
    g_xb[gid] = __float2bfloat16(x[((size_t)n * NS + s) * D + d]);
}

__global__ void conv_c_kernel(int cur) {
    __shared__ float part[2];
    const int s = blockIdx.y, k = blockIdx.x, t = threadIdx.x;   // t < 64
    size_t idx = ((size_t)s * NC + k) * D + t;
    float v = g_c[cur][idx];
    __nv_bfloat16 h = __float2bfloat16(v);
    __nv_bfloat16 l = __float2bfloat16(v - __bfloat162float(h));
    g_ch[idx] = h;
    g_cl[idx] = l;
    float sq = v * v;
#pragma unroll
    for (int o = 16; o > 0; o >>= 1) sq += __shfl_down_sync(0xffffffffu, sq, o);
    if ((t & 31) == 0) part[t >> 5] = sq;
    __syncthreads();
    if (t == 0) g_c2[s * NC + k] = part[0] + part[1];
}

// ---------------- gemm: 2 A-tiles per CTA, shared B, pipelined fills ----------------
#define SM_C2     0                     // 1 KB
#define SM_MINKEY 1024                  // 512 B
#define SM_CCNT   1536                  // 512 B
#define SM_CAND   2048                  // 2 KB
#define SM_HIST   4096                  // 1 KB
#define SM_KEY64  5120                  // 1 KB
#define SM_PAIRS  6144                  // 4 KB
#define SM_OVF    10240                 // 512 B
#define SM_CNTRS  10752                 // 512 B
#define SM_A0     11264                 // 16 KB
#define SM_A1     27648                 // 16 KB
#define SM_B0H    44032                 // 16 KB
#define SM_B0L    60416                 // 16 KB
#define SM_B1H    76800                 // 16 KB
#define SM_B1L    93184                 // 16 KB
#define SM_TOTAL  109568                // 107 KB -> 2 CTAs/SM

__global__ __launch_bounds__(256, 2)
void gemm_assign_kernel(const float* __restrict__ x, int cur) {
    extern __shared__ char smem[];
    const uint32_t sb = smem_u32(smem);
    const int tid = threadIdx.x;
    const int wid = tid >> 5, lane = tid & 31;
    const int s = blockIdx.y;
    const int tile0 = blockIdx.x * 2;

    float*              c2s    = (float*)(smem + SM_C2);
    uint32_t*           minkey = (uint32_t*)(smem + SM_MINKEY);
    uint32_t*           ccnt   = (uint32_t*)(smem + SM_CCNT);
    unsigned char*      cand   = (unsigned char*)(smem + SM_CAND);
    int*                hist   = (int*)(smem + SM_HIST);
    unsigned long long* key64  = (unsigned long long*)(smem + SM_KEY64);
    unsigned short*     pairs  = (unsigned short*)(smem + SM_PAIRS);
    unsigned char*      ovfl   = (unsigned char*)(smem + SM_OVF);
    uint32_t*           cntrs  = (uint32_t*)(smem + SM_CNTRS);

    // ---- prologue fills: group0 = A(t0)+B0; group1 = B1; group2 = A(t1) ----
    {
        const uint4* gA0  = (const uint4*)(g_xb + ((size_t)s * NPTS + (size_t)tile0 * TILE_M) * D);
        const uint4* gB0h = (const uint4*)(g_ch + (size_t)s * NC * D);
        const uint4* gB0l = (const uint4*)(g_cl + (size_t)s * NC * D);
#pragma unroll
        for (int i = tid; i < TILE_M * 8; i += 256) {
            uint32_t sw = SW128((uint32_t)(i * 16));
            CP16(sb + SM_A0 + sw, gA0 + i);
            CP16(sb + SM_B0H + sw, gB0h + i);
            CP16(sb + SM_B0L + sw, gB0l + i);
        }
        CP_COMMIT();
        const uint4* gB1h = (const uint4*)(g_ch + ((size_t)s * NC + 128) * D);
        const uint4* gB1l = (const uint4*)(g_cl + ((size_t)s * NC + 128) * D);
#pragma unroll
        for (int i = tid; i < 128 * 8; i += 256) {
            uint32_t sw = SW128((uint32_t)(i * 16));
            CP16(sb + SM_B1H + sw, gB1h + i);
            CP16(sb + SM_B1L + sw, gB1l + i);
        }
        CP_COMMIT();
        const uint4* gA1 = (const uint4*)(g_xb + ((size_t)s * NPTS + (size_t)(tile0 + 1) * TILE_M) * D);
#pragma unroll
        for (int i = tid; i < TILE_M * 8; i += 256) {
            uint32_t sw = SW128((uint32_t)(i * 16));
            CP16(sb + SM_A1 + sw, gA1 + i);
        }
        CP_COMMIT();
    }
    c2s[tid] = g_c2[s * NC + tid];
    hist[tid] = 0;
    if (tid < TILE_M) {
        minkey[tid] = 0xFFFFFFFFu;
        ccnt[tid]   = 0;
        key64[tid]  = 0xFFFFFFFFFFFFFFFFull;
    }
    if (tid < 2) cntrs[tid] = 0;

    // ---- warp tiling: 2 (M) x 4 (N); per chunk warp tile 64 x 32 ----
    const int mo = (wid >> 2) * 64;
    const int nwarp = wid & 3;
    const int gq = lane >> 2;
    const int tg = lane & 3;
    const int ac = tg * 2;

    const int arow_l  = ((lane >> 3) & 1) * 8 + (lane & 7);
    const int akoff_l = (lane >> 4) * 16;
    const int brow_l  = nwarp * 32 + ((lane >> 4) & 1) * 8 + (lane & 7);
    const int bkoff_l = ((lane >> 3) & 1) * 16;

    uint32_t relA[4];
#pragma unroll
    for (int mf = 0; mf < 4; mf++) {
        int R = mo + mf * 16 + arow_l;
        relA[mf] = R * 128 + (uint32_t)(akoff_l ^ ((R & 7) << 4));
    }
    uint32_t relB[2];
#pragma unroll
    for (int nfp = 0; nfp < 2; nfp++) {
        int R = brow_l + nfp * 16;
        relB[nfp] = R * 128 + (uint32_t)(bkoff_l ^ ((R & 7) << 4));
    }

#pragma unroll 1
    for (int t = 0; t < 2; t++) {
        const int tile = tile0 + t;
        const uint32_t aBase = sb + (t ? SM_A1 : SM_A0);

#pragma unroll
        for (int c = 0; c < 2; c++) {
            if (t == 0) {
                if (c == 0) { CP_WAIT(2); } else { CP_WAIT(1); }
            } else if (c == 0) {
                CP_WAIT(0);
            }
            __syncthreads();   // fills + per-tile state reset visible

            const uint32_t bH = (c == 0) ? (sb + SM_B0H) : (sb + SM_B1H);
            const uint32_t bL = bH + 16384;

            float acc[4][4][4];
#pragma unroll
            for (int mf = 0; mf < 4; mf++)
#pragma unroll
                for (int nf = 0; nf < 4; nf++)
#pragma unroll
                    for (int r = 0; r < 4; r++) acc[mf][nf][r] = 0.f;

#pragma unroll
            for (int ks = 0; ks < 4; ks++) {
                const uint32_t kx = (uint32_t)(ks * 32);

                uint32_t aF[4][4];
#pragma unroll
                for (int mf = 0; mf < 4; mf++)
                    LDSM_X4(aF[mf][0], aF[mf][1], aF[mf][2], aF[mf][3],
                            aBase + (relA[mf] ^ kx));
                uint32_t bh[2][4];
#pragma unroll
                for (int nfp = 0; nfp < 2; nfp++)
                    LDSM_X4(bh[nfp][0], bh[nfp][1], bh[nfp][2], bh[nfp][3],
                            bH + (relB[nfp] ^ kx));
                // Ah * Bh
#pragma unroll
                for (int nfp = 0; nfp < 2; nfp++)
#pragma unroll
                    for (int mf = 0; mf < 4; mf++) {
                        mma16816(acc[mf][2 * nfp],     aF[mf], bh[nfp][0], bh[nfp][1]);
                        mma16816(acc[mf][2 * nfp + 1], aF[mf], bh[nfp][2], bh[nfp][3]);
                    }
                // Ah * Bl
#pragma unroll
                for (int nfp = 0; nfp < 2; nfp++) {
                    uint32_t bl[4];
                    LDSM_X4(bl[0], bl[1], bl[2], bl[3], bL + (relB[nfp] ^ kx));
#pragma unroll
                    for (int mf = 0; mf < 4; mf++) {
                        mma16816(acc[mf][2 * nfp],     aF[mf], bl[0], bl[1]);
                        mma16816(acc[mf][2 * nfp + 1], aF[mf], bl[2], bl[3]);
                    }
                }
            }

            // ---- keys + per-row min ----
            uint32_t keys[4][4][4];
#pragma unroll
            for (int mf = 0; mf < 4; mf++)
#pragma unroll
                for (int nf = 0; nf < 4; nf++)
#pragma unroll
                    for (int r = 0; r < 4; r++) {
                        const int col = c * 128 + nwarp * 32 + nf * 8 + ac + (r & 1);
                        float dist = __fmaf_rn(-2.f, acc[mf][nf][r], c2s[col]);
                        keys[mf][nf][r] = (ford(dist) & 0xFFFFFF00u) | (uint32_t)col;
                    }
#pragma unroll
            for (int mf = 0; mf < 4; mf++)
#pragma unroll
                for (int half = 0; half < 2; half++) {
                    const int row = mo + mf * 16 + half * 8 + gq;
                    uint32_t m = keys[mf][0][half * 2];
                    m = min(m, keys[mf][0][half * 2 + 1]);
#pragma unroll
                    for (int nf = 1; nf < 4; nf++) {
                        m = min(m, keys[mf][nf][half * 2]);
                        m = min(m, keys[mf][nf][half * 2 + 1]);
                    }
                    atomicMin(&minkey[row], m);
                }
            __syncthreads();

            // ---- threshold scan + candidate append ----
#pragma unroll
            for (int mf = 0; mf < 4; mf++)
#pragma unroll
                for (int half = 0; half < 2; half++) {
                    const int row = mo + mf * 16 + half * 8 + gq;
                    float bestd = funord(minkey[row] & 0xFFFFFF00u);
                    uint32_t thrkey = ford(bestd + MARGIN) | 0xFFu;
#pragma unroll
                    for (int nf = 0; nf < 4; nf++)
#pragma unroll
                        for (int rr = 0; rr < 2; rr++) {
                            uint32_t kkey = keys[mf][nf][half * 2 + rr];
                            if (kkey <= thrkey) {
                                uint32_t pos = atomicAdd(&ccnt[row], 1u);
                                if (pos < CAP)
                                    cand[row * CAP + pos] = (unsigned char)(kkey & 0xFFu);
                            }
                        }
                }
            __syncthreads();
        }

        // ---- build load-balanced worklist ----
        if (tid < TILE_M) {
            uint32_t n = ccnt[tid];
            if (n > CAP) {
                uint32_t op = atomicAdd(&cntrs[1], 1u);
                ovfl[op] = (unsigned char)tid;
            } else {
                uint32_t basep = atomicAdd(&cntrs[0], n);
                for (uint32_t j = 0; j < n; j++)
                    pairs[basep + j] =
                        (unsigned short)((tid << 8) | cand[tid * CAP + j]);
            }
        }
        __syncthreads();

        // ---- exact fp32 re-rank: pairs round-robin over 256 threads ----
        {
            const uint32_t npairs = cntrs[0];
            for (uint32_t i = tid; i < npairs; i += 256) {
                const unsigned short pr = pairs[i];
                const int row = pr >> 8, k0 = pr & 0xFF;
                const int p = tile * TILE_M + row;
                const float4* x4 = (const float4*)(x + ((size_t)p * NS + s) * D);
                const float4* c4 = (const float4*)(g_c[cur] + ((size_t)s * NC + k0) * D);
                float da = 0.f, db = 0.f;
#pragma unroll
                for (int i2 = 0; i2 < 16; i2 += 2) {
                    float4 xv = x4[i2], cv = c4[i2];
                    da = __fmaf_rn(xv.x, cv.x, da); da = __fmaf_rn(xv.y, cv.y, da);
                    da = __fmaf_rn(xv.z, cv.z, da); da = __fmaf_rn(xv.w, cv.w, da);
                    float4 xw = x4[i2 + 1], cw = c4[i2 + 1];
                    db = __fmaf_rn(xw.x, cw.x, db); db = __fmaf_rn(xw.y, cw.y, db);
                    db = __fmaf_rn(xw.z, cw.z, db); db = __fmaf_rn(xw.w, cw.w, db);
                }
                float dist = __fmaf_rn(-2.f, da + db, c2s[k0]);
                unsigned long long key =
                    ((unsigned long long)ford(dist) << 8) | (unsigned long long)k0;
                atomicMin(&key64[row], key);
            }
            // overflow rows: block-cooperative full scan (1 centroid per thread)
            const uint32_t novf = cntrs[1];
            for (uint32_t j = 0; j < novf; j++) {
                const int row = ovfl[j];
                const int p = tile * TILE_M + row;
                const int k0 = tid;
                const float4* x4 = (const float4*)(x + ((size_t)p * NS + s) * D);
                const float4* c4 = (const float4*)(g_c[cur] + ((size_t)s * NC + k0) * D);
                float da = 0.f, db = 0.f;
#pragma unroll
                for (int i2 = 0; i2 < 16; i2 += 2) {
                    float4 xv = x4[i2], cv = c4[i2];
                    da = __fmaf_rn(xv.x, cv.x, da); da = __fmaf_rn(xv.y, cv.y, da);
                    da = __fmaf_rn(xv.z, cv.z, da); da = __fmaf_rn(xv.w, cv.w, da);
                    float4 xw = x4[i2 + 1], cw = c4[i2 + 1];
                    db = __fmaf_rn(xw.x, cw.x, db); db = __fmaf_rn(xw.y, cw.y, db);
                    db = __fmaf_rn(xw.z, cw.z, db); db = __fmaf_rn(xw.w, cw.w, db);
                }
                float dist = __fmaf_rn(-2.f, da + db, c2s[k0]);
                unsigned long long key =
                    ((unsigned long long)ford(dist) << 8) | (unsigned long long)k0;
                atomicMin(&key64[row], key);
            }
        }
        __syncthreads();

        if (tid < TILE_M) {
            int bk = (int)(key64[tid] & 0xFFull);
            g_assign[s * NPTS + tile * TILE_M + tid] = (unsigned char)bk;
            atomicAdd(&hist[bk], 1);
        }
        __syncthreads();

        g_bh[((size_t)s * NC + tid) * NTILE + tile] = hist[tid];
        __syncthreads();   // hist reads done before reset

        // ---- reset per-tile state for tile1 ----
        if (t == 0) {
            hist[tid] = 0;
            if (tid < TILE_M) {
                minkey[tid] = 0xFFFFFFFFu;
                ccnt[tid]   = 0;
                key64[tid]  = 0xFFFFFFFFFFFFFFFFull;
            }
            if (tid < 2) cntrs[tid] = 0;
            // ordering to first use is provided by the sync at chunk entry
        }
    }
}

// ---------------- scan phase 1: one warp per (s,k) row, chip-wide ----------------
__global__ void scan_row_kernel() {
    const int s = blockIdx.y;
    const int k = blockIdx.x * 8 + (threadIdx.x >> 5);
    const int lane = threadIdx.x & 31;
    const int4* src = (const int4*)(g_bh + ((size_t)s * NC + k) * NTILE);
    int4*       dst = (int4*)(g_bhoff + ((size_t)s * NC + k) * NTILE);

    int4 a = src[lane * 2];
    int4 b = src[lane * 2 + 1];
    int p0 = 0;
    int p1 = p0 + a.x, p2 = p1 + a.y, p3 = p2 + a.z;
    int p4 = p3 + a.w, p5 = p4 + b.x, p6 = p5 + b.y, p7 = p6 + b.z;
    int tot = p7 + b.w;

    int incl = tot;
#pragma unroll
    for (int o = 1; o < 32; o <<= 1) {
        int n = __shfl_up_sync(0xffffffffu, incl, o);
        if (lane >= o) incl += n;
    }
    int excl = incl - tot;

    dst[lane * 2]     = make_int4(excl + p0, excl + p1, excl + p2, excl + p3);
    dst[lane * 2 + 1] = make_int4(excl + p4, excl + p5, excl + p6, excl + p7);
    if (lane == 31) g_cnt[s * NC + k] = incl;
}

// ---------------- scan phase 2: cross-k exclusive scan ----------------
__global__ void scan_off_kernel() {
    __shared__ int sm[NC];
    const int s = blockIdx.x, k = threadIdx.x;
    int v = g_cnt[s * NC + k];
    sm[k] = v;
    __syncthreads();
    for (int o = 1; o < NC; o <<= 1) {
        int add = (k >= o) ? sm[k - o] : 0;
        __syncthreads();
        sm[k] += add;
        __syncthreads();
    }
    g_off[s * NC + k] = sm[k] - v;
}

// ---------------- scatter ----------------
__global__ void scatter_kernel() {
    __shared__ int warp_hist[4][NC];
    const int s = blockIdx.y, b = blockIdx.x;
    const int tid = threadIdx.x, w = tid >> 5, lane = tid & 31;

    for (int i = tid; i < 4 * NC; i += 128)
        (&warp_hist[0][0])[i] = 0;
    __syncthreads();

    const int p = b * TILE_M + tid;
    const int a = g_assign[s * NPTS + p];

    unsigned mask = __match_any_sync(0xffffffffu, a);
    int lrank  = __popc(mask & ((1u << lane) - 1));
    int leader = __ffs(mask) - 1;
    if (lane == leader) warp_hist[w][a] = __popc(mask);
    __syncthreads();

    int pre = 0;
#pragma unroll
    for (int ww = 0; ww < 4; ww++)
        if (ww < w) pre += warp_hist[ww][a];

    int pos = g_off[s * NC + a]
            + g_bhoff[((size_t)s * NC + a) * NTILE + b]
            + pre + lrank;
    g_bucket[s * NPTS + pos] = (unsigned short)p;
}

// ---------------- update: float4 gather (16 streams x 16 lanes) ----------------
__global__ void update_kernel(const float* __restrict__ x, int cursel,
                              float* __restrict__ outp) {
    __shared__ unsigned short sl[256];
    __shared__ float4 part4[256];
    __shared__ float c2p[2];
    const int s = blockIdx.y, k = blockIdx.x, t = threadIdx.x;  // 256 threads
    const int g = t >> 4, l = t & 15;     // point-stream / float4-lane
    const int base  = s * NC + k;
    const int start = g_off[base];
    const int count = g_cnt[base];

    float4 acc = make_float4(0.f, 0.f, 0.f, 0.f);
    for (int b = 0; b < count; b += 256) {
        int m = min(256, count - b);
        if (t < m) sl[t] = g_bucket[s * NPTS + start + b + t];
        __syncthreads();
        for (int i = g; i < m; i += 16) {
            float4 v = *(const float4*)(x + ((size_t)sl[i] * NS + s) * D + l * 4);
            acc.x += v.x; acc.y += v.y; acc.z += v.z; acc.w += v.w;
        }
        __syncthreads();
    }
    part4[t] = acc;
    __syncthreads();

    if (t < 64) {                         // t = dim
        const int lq = t >> 2, comp = t & 3;
        float sum = 0.f;
#pragma unroll
        for (int gg = 0; gg < 16; gg++) {
            float4 v = part4[gg * 16 + lq];
            sum += (comp == 0) ? v.x : (comp == 1) ? v.y : (comp == 2) ? v.z : v.w;
        }
        size_t idx = (size_t)base * D + t;
        float res = (count > 0) ? (sum / (float)count) : g_c[cursel][idx];
        float* dst = outp ? outp : g_c[1 - cursel];
        dst[idx] = res;
        __nv_bfloat16 h = __float2bfloat16(res);
        __nv_bfloat16 lo = __float2bfloat16(res - __bfloat162float(h));
        g_ch[idx] = h;
        g_cl[idx] = lo;
        float sq = res * res;
#pragma unroll
        for (int o = 16; o > 0; o >>= 1) sq += __shfl_down_sync(0xffffffffu, sq, o);
        if ((t & 31) == 0) c2p[t >> 5] = sq;
    }
    __syncthreads();
    if (t == 0) g_c2[base] = c2p[0] + c2p[1];
}

// ---------------- launch ----------------
extern "C" void kernel_launch(void* const* d_in, const int* in_sizes, int n_in,
                              void* d_out, int out_size) {
    const float* x = (const float*)d_in[0];
    float* out = (float*)d_out;

    cudaFuncSetAttribute(gemm_assign_kernel,
                         cudaFuncAttributeMaxDynamicSharedMemorySize, SM_TOTAL);

    init_c_kernel<<<(NS * NC * D) / 256, 256>>>(x);
    init_xb_kernel<<<(NS * NPTS * D) / 256, 256>>>(x);
    conv_c_kernel<<<dim3(NC, NS), 64>>>(0);

    int cur = 0;
    for (int it = 0; it < NITER; ++it) {
        gemm_assign_kernel<<<dim3(NTILE / 2, NS), 256, SM_TOTAL>>>(x, cur);
        scan_row_kernel<<<dim3(NC / 8, NS), 256>>>();
        scan_off_kernel<<<NS, NC>>>();
        scatter_kernel<<<dim3(NTILE, NS), 128>>>();
        update_kernel<<<dim3(NC, NS), 256>>>(x, cur,
                                             (it == NITER - 1) ? out : nullptr);
        cur ^= 1;
    }
}

// round 17
// speedup vs baseline: 1.2147x; 1.2147x over previous
#include <cuda_runtime.h>
#include <cuda_bf16.h>
#include <cstdint>

#define NS     16
#define NC     256
#define D      64
#define NPTS   32768
#define NITER  5
#define TILE_M 128
#define NTILE  (NPTS / TILE_M)   // 256 tiles per space
#define CAP    16
#define MARGIN 0.5f

// ---------------- scratch ----------------
__device__ float          g_c[2][NS * NC * D];
__device__ __nv_bfloat16  g_xb[NS * NPTS * D];      // bf16(x)
__device__ __nv_bfloat16  g_cb[NS * NC * D];        // bf16(c)
__device__ float          g_c2[NS * NC];
__device__ unsigned char  g_assign[NS * NPTS];
__device__ unsigned short g_bucket[NS * NPTS];
__device__ int            g_cnt[NS * NC];
__device__ int            g_off[NS * NC];
__device__ __align__(16) int g_bh[NS * NC * NTILE];     // [s][k][tile]
__device__ __align__(16) int g_bhoff[NS * NC * NTILE];  // [s][k][tile]

#define SW128(off) ((off) ^ (((off) >> 3) & 0x70))

__device__ __forceinline__ uint32_t smem_u32(const void* p) {
    uint32_t a;
    asm("{ .reg .u64 t; cvta.to.shared.u64 t, %1; cvt.u32.u64 %0, t; }"
        : "=r"(a) : "l"(p));
    return a;
}

#define LDSM_X4(r0, r1, r2, r3, addr) \
    asm volatile("ldmatrix.sync.aligned.m8n8.x4.shared.b16 {%0,%1,%2,%3}, [%4];" \
        : "=r"(r0), "=r"(r1), "=r"(r2), "=r"(r3) : "r"(addr))

#define CP16(dst, src) \
    asm volatile("cp.async.cg.shared.global [%0], [%1], 16;" :: "r"(dst), "l"(src))
#define CP_COMMIT() asm volatile("cp.async.commit_group;")
#define CP_WAIT(n)  asm volatile("cp.async.wait_group %0;" :: "n"(n))

__device__ __forceinline__ void mma16816(float* c, const uint32_t* a,
                                         uint32_t b0, uint32_t b1) {
    asm("mma.sync.aligned.m16n8k16.row.col.f32.bf16.bf16.f32 "
        "{%0,%1,%2,%3}, {%4,%5,%6,%7}, {%8,%9}, {%0,%1,%2,%3};"
        : "+f"(c[0]), "+f"(c[1]), "+f"(c[2]), "+f"(c[3])
        : "r"(a[0]), "r"(a[1]), "r"(a[2]), "r"(a[3]), "r"(b0), "r"(b1));
}

// monotone float <-> ordered-uint
__device__ __forceinline__ uint32_t ford(float f) {
    uint32_t u = __float_as_uint(f);
    return u ^ (uint32_t)(((int32_t)u >> 31) | 0x80000000);
}
__device__ __forceinline__ float funord(uint32_t u) {
    uint32_t v = (u & 0x80000000u) ? (u ^ 0x80000000u) : ~u;
    return __uint_as_float(v);
}

// ---------------- init ----------------
__global__ void init_c_kernel(const float* __restrict__ x) {
    int gid = blockIdx.x * blockDim.x + threadIdx.x;
    int d = gid & 63;
    int k = (gid >> 6) & 255;
    int s = gid >> 14;
    g_c[0][gid] = x[((size_t)k * NS + s) * D + d];
}

__global__ void init_xb_kernel(const float* __restrict__ x) {
    int gid = blockIdx.x * blockDim.x + threadIdx.x;
    int d = gid & 63;
    int n = (gid >> 6) & (NPTS - 1);
    int s = gid >> 21;
    g_xb[gid] = __float2bfloat16(x[((size_t)n * NS + s) * D + d]);
}

__global__ void conv_c_kernel(int cur) {
    __shared__ float part[2];
    const int s = blockIdx.y, k = blockIdx.x, t = threadIdx.x;   // t < 64
    size_t idx = ((size_t)s * NC + k) * D + t;
    float v = g_c[cur][idx];
    g_cb[idx] = __float2bfloat16(v);
    float sq = v * v;
#pragma unroll
    for (int o = 16; o > 0; o >>= 1) sq += __shfl_down_sync(0xffffffffu, sq, o);
    if ((t & 31) == 0) part[t >> 5] = sq;
    __syncthreads();
    if (t == 0) g_c2[s * NC + k] = part[0] + part[1];
}

// ---------------- gemm (1-pass bf16) + key-min + exact re-rank ----------------
#define SM_C2     0                     // 1 KB
#define SM_MINKEY 1024                  // 512 B
#define SM_CCNT   1536                  // 512 B
#define SM_CAND   2048                  // 2 KB
#define SM_HIST   4096                  // 1 KB
#define SM_KEY64  5120                  // 1 KB
#define SM_PAIRS  6144                  // 4 KB
#define SM_OVF    10240                 // 512 B
#define SM_CNTRS  10752                 // 512 B
#define SM_A      11264                 // 16 KB
#define SM_B0     27648                 // 16 KB
#define SM_B1     44032                 // 16 KB
#define SM_TOTAL  60416                 // 59 KB -> 2 CTAs/SM (reg-bound)

__global__ __launch_bounds__(256, 2)
void gemm_assign_kernel(const float* __restrict__ x, int cur) {
    extern __shared__ char smem[];
    const uint32_t sb = smem_u32(smem);
    const int tid = threadIdx.x;
    const int wid = tid >> 5, lane = tid & 31;
    const int s = blockIdx.y, tile = blockIdx.x;

    float*              c2s    = (float*)(smem + SM_C2);
    uint32_t*           minkey = (uint32_t*)(smem + SM_MINKEY);
    uint32_t*           ccnt   = (uint32_t*)(smem + SM_CCNT);
    unsigned char*      cand   = (unsigned char*)(smem + SM_CAND);
    int*                hist   = (int*)(smem + SM_HIST);
    unsigned long long* key64  = (unsigned long long*)(smem + SM_KEY64);
    unsigned short*     pairs  = (unsigned short*)(smem + SM_PAIRS);
    unsigned char*      ovfl   = (unsigned char*)(smem + SM_OVF);
    uint32_t*           cntrs  = (uint32_t*)(smem + SM_CNTRS);

    // ---- async fills: group0 = A + B0; group1 = B1 ----
    {
        const uint4* gA  = (const uint4*)(g_xb + ((size_t)s * NPTS + (size_t)tile * TILE_M) * D);
        const uint4* gB0 = (const uint4*)(g_cb + (size_t)s * NC * D);
#pragma unroll
        for (int i = tid; i < TILE_M * 8; i += 256) {
            uint32_t sw = SW128((uint32_t)(i * 16));
            CP16(sb + SM_A + sw, gA + i);
            CP16(sb + SM_B0 + sw, gB0 + i);
        }
        CP_COMMIT();
        const uint4* gB1 = (const uint4*)(g_cb + ((size_t)s * NC + 128) * D);
#pragma unroll
        for (int i = tid; i < 128 * 8; i += 256) {
            uint32_t sw = SW128((uint32_t)(i * 16));
            CP16(sb + SM_B1 + sw, gB1 + i);
        }
        CP_COMMIT();
    }
    c2s[tid] = g_c2[s * NC + tid];
    hist[tid] = 0;
    if (tid < TILE_M) {
        minkey[tid] = 0xFFFFFFFFu;
        ccnt[tid]   = 0;
        key64[tid]  = 0xFFFFFFFFFFFFFFFFull;
    }
    if (tid < 2) cntrs[tid] = 0;

    // ---- warp tiling: 2 (M) x 4 (N); per chunk warp tile 64 x 32 ----
    const int mo = (wid >> 2) * 64;
    const int nwarp = wid & 3;
    const int gq = lane >> 2;
    const int tg = lane & 3;
    const int ac = tg * 2;

    const int arow_l  = ((lane >> 3) & 1) * 8 + (lane & 7);
    const int akoff_l = (lane >> 4) * 16;
    const int brow_l  = nwarp * 32 + ((lane >> 4) & 1) * 8 + (lane & 7);
    const int bkoff_l = ((lane >> 3) & 1) * 16;

    uint32_t relA[4];
#pragma unroll
    for (int mf = 0; mf < 4; mf++) {
        int R = mo + mf * 16 + arow_l;
        relA[mf] = SM_A + R * 128 + (uint32_t)(akoff_l ^ ((R & 7) << 4));
    }
    uint32_t relB[2];
#pragma unroll
    for (int nfp = 0; nfp < 2; nfp++) {
        int R = brow_l + nfp * 16;
        relB[nfp] = R * 128 + (uint32_t)(bkoff_l ^ ((R & 7) << 4));
    }

#pragma unroll
    for (int c = 0; c < 2; c++) {
        if (c == 0) { CP_WAIT(1); } else { CP_WAIT(0); }
        __syncthreads();

        const uint32_t bB = (c == 0) ? (sb + SM_B0) : (sb + SM_B1);

        float acc[4][4][4];
#pragma unroll
        for (int mf = 0; mf < 4; mf++)
#pragma unroll
            for (int nf = 0; nf < 4; nf++)
#pragma unroll
                for (int r = 0; r < 4; r++) acc[mf][nf][r] = 0.f;

#pragma unroll
        for (int ks = 0; ks < 4; ks++) {
            const uint32_t kx = (uint32_t)(ks * 32);

            uint32_t aF[4][4];
#pragma unroll
            for (int mf = 0; mf < 4; mf++)
                LDSM_X4(aF[mf][0], aF[mf][1], aF[mf][2], aF[mf][3],
                        sb + (relA[mf] ^ kx));
            uint32_t bF[2][4];
#pragma unroll
            for (int nfp = 0; nfp < 2; nfp++)
                LDSM_X4(bF[nfp][0], bF[nfp][1], bF[nfp][2], bF[nfp][3],
                        bB + (relB[nfp] ^ kx));
#pragma unroll
            for (int nfp = 0; nfp < 2; nfp++)
#pragma unroll
                for (int mf = 0; mf < 4; mf++) {
                    mma16816(acc[mf][2 * nfp],     aF[mf], bF[nfp][0], bF[nfp][1]);
                    mma16816(acc[mf][2 * nfp + 1], aF[mf], bF[nfp][2], bF[nfp][3]);
                }
        }

        // ---- keys + per-row min ----
        uint32_t keys[4][4][4];
#pragma unroll
        for (int mf = 0; mf < 4; mf++)
#pragma unroll
            for (int nf = 0; nf < 4; nf++)
#pragma unroll
                for (int r = 0; r < 4; r++) {
                    const int col = c * 128 + nwarp * 32 + nf * 8 + ac + (r & 1);
                    float dist = __fmaf_rn(-2.f, acc[mf][nf][r], c2s[col]);
                    keys[mf][nf][r] = (ford(dist) & 0xFFFFFF00u) | (uint32_t)col;
                }
#pragma unroll
        for (int mf = 0; mf < 4; mf++)
#pragma unroll
            for (int half = 0; half < 2; half++) {
                const int row = mo + mf * 16 + half * 8 + gq;
                uint32_t m = keys[mf][0][half * 2];
                m = min(m, keys[mf][0][half * 2 + 1]);
#pragma unroll
                for (int nf = 1; nf < 4; nf++) {
                    m = min(m, keys[mf][nf][half * 2]);
                    m = min(m, keys[mf][nf][half * 2 + 1]);
                }
                atomicMin(&minkey[row], m);
            }
        __syncthreads();

        // ---- threshold scan + candidate append ----
#pragma unroll
        for (int mf = 0; mf < 4; mf++)
#pragma unroll
            for (int half = 0; half < 2; half++) {
                const int row = mo + mf * 16 + half * 8 + gq;
                float bestd = funord(minkey[row] & 0xFFFFFF00u);
                uint32_t thrkey = ford(bestd + MARGIN) | 0xFFu;
#pragma unroll
                for (int nf = 0; nf < 4; nf++)
#pragma unroll
                    for (int rr = 0; rr < 2; rr++) {
                        uint32_t kkey = keys[mf][nf][half * 2 + rr];
                        if (kkey <= thrkey) {
                            uint32_t pos = atomicAdd(&ccnt[row], 1u);
                            if (pos < CAP)
                                cand[row * CAP + pos] = (unsigned char)(kkey & 0xFFu);
                        }
                    }
            }
        __syncthreads();
    }

    // ---- build load-balanced worklist ----
    if (tid < TILE_M) {
        uint32_t n = ccnt[tid];
        if (n > CAP) {
            uint32_t op = atomicAdd(&cntrs[1], 1u);
            ovfl[op] = (unsigned char)tid;
        } else {
            uint32_t basep = atomicAdd(&cntrs[0], n);
            for (uint32_t j = 0; j < n; j++)
                pairs[basep + j] =
                    (unsigned short)((tid << 8) | cand[tid * CAP + j]);
        }
    }
    __syncthreads();

    // ---- exact fp32 re-rank: pairs round-robin over 256 threads ----
    {
        const uint32_t npairs = cntrs[0];
        for (uint32_t i = tid; i < npairs; i += 256) {
            const unsigned short pr = pairs[i];
            const int row = pr >> 8, k0 = pr & 0xFF;
            const int p = tile * TILE_M + row;
            const float4* x4 = (const float4*)(x + ((size_t)p * NS + s) * D);
            const float4* c4 = (const float4*)(g_c[cur] + ((size_t)s * NC + k0) * D);
            float da = 0.f, db = 0.f;
#pragma unroll
            for (int i2 = 0; i2 < 16; i2 += 2) {
                float4 xv = x4[i2], cv = c4[i2];
                da = __fmaf_rn(xv.x, cv.x, da); da = __fmaf_rn(xv.y, cv.y, da);
                da = __fmaf_rn(xv.z, cv.z, da); da = __fmaf_rn(xv.w, cv.w, da);
                float4 xw = x4[i2 + 1], cw = c4[i2 + 1];
                db = __fmaf_rn(xw.x, cw.x, db); db = __fmaf_rn(xw.y, cw.y, db);
                db = __fmaf_rn(xw.z, cw.z, db); db = __fmaf_rn(xw.w, cw.w, db);
            }
            float dist = __fmaf_rn(-2.f, da + db, c2s[k0]);
            unsigned long long key =
                ((unsigned long long)ford(dist) << 8) | (unsigned long long)k0;
            atomicMin(&key64[row], key);
        }
        // overflow rows: block-cooperative full scan (1 centroid per thread)
        const uint32_t novf = cntrs[1];
        for (uint32_t j = 0; j < novf; j++) {
            const int row = ovfl[j];
            const int p = tile * TILE_M + row;
            const int k0 = tid;
            const float4* x4 = (const float4*)(x + ((size_t)p * NS + s) * D);
            const float4* c4 = (const float4*)(g_c[cur] + ((size_t)s * NC + k0) * D);
            float da = 0.f, db = 0.f;
#pragma unroll
            for (int i2 = 0; i2 < 16; i2 += 2) {
                float4 xv = x4[i2], cv = c4[i2];
                da = __fmaf_rn(xv.x, cv.x, da); da = __fmaf_rn(xv.y, cv.y, da);
                da = __fmaf_rn(xv.z, cv.z, da); da = __fmaf_rn(xv.w, cv.w, da);
                float4 xw = x4[i2 + 1], cw = c4[i2 + 1];
                db = __fmaf_rn(xw.x, cw.x, db); db = __fmaf_rn(xw.y, cw.y, db);
                db = __fmaf_rn(xw.z, cw.z, db); db = __fmaf_rn(xw.w, cw.w, db);
            }
            float dist = __fmaf_rn(-2.f, da + db, c2s[k0]);
            unsigned long long key =
                ((unsigned long long)ford(dist) << 8) | (unsigned long long)k0;
            atomicMin(&key64[row], key);
        }
    }
    __syncthreads();

    if (tid < TILE_M) {
        int bk = (int)(key64[tid] & 0xFFull);
        g_assign[s * NPTS + tile * TILE_M + tid] = (unsigned char)bk;
        atomicAdd(&hist[bk], 1);
    }
    __syncthreads();

    g_bh[((size_t)s * NC + tid) * NTILE + tile] = hist[tid];
}

// ---------------- scan phase 1: one warp per (s,k) row, chip-wide ----------------
__global__ void scan_row_kernel() {
    const int s = blockIdx.y;
    const int k = blockIdx.x * 8 + (threadIdx.x >> 5);
    const int lane = threadIdx.x & 31;
    const int4* src = (const int4*)(g_bh + ((size_t)s * NC + k) * NTILE);
    int4*       dst = (int4*)(g_bhoff + ((size_t)s * NC + k) * NTILE);

    int4 a = src[lane * 2];
    int4 b = src[lane * 2 + 1];
    int p0 = 0;
    int p1 = p0 + a.x, p2 = p1 + a.y, p3 = p2 + a.z;
    int p4 = p3 + a.w, p5 = p4 + b.x, p6 = p5 + b.y, p7 = p6 + b.z;
    int tot = p7 + b.w;

    int incl = tot;
#pragma unroll
    for (int o = 1; o < 32; o <<= 1) {
        int n = __shfl_up_sync(0xffffffffu, incl, o);
        if (lane >= o) incl += n;
    }
    int excl = incl - tot;

    dst[lane * 2]     = make_int4(excl + p0, excl + p1, excl + p2, excl + p3);
    dst[lane * 2 + 1] = make_int4(excl + p4, excl + p5, excl + p6, excl + p7);
    if (lane == 31) g_cnt[s * NC + k] = incl;
}

// ---------------- scan phase 2: cross-k exclusive scan ----------------
__global__ void scan_off_kernel() {
    __shared__ int sm[NC];
    const int s = blockIdx.x, k = threadIdx.x;
    int v = g_cnt[s * NC + k];
    sm[k] = v;
    __syncthreads();
    for (int o = 1; o < NC; o <<= 1) {
        int add = (k >= o) ? sm[k - o] : 0;
        __syncthreads();
        sm[k] += add;
        __syncthreads();
    }
    g_off[s * NC + k] = sm[k] - v;
}

// ---------------- scatter ----------------
__global__ void scatter_kernel() {
    __shared__ int warp_hist[4][NC];
    const int s = blockIdx.y, b = blockIdx.x;
    const int tid = threadIdx.x, w = tid >> 5, lane = tid & 31;

    for (int i = tid; i < 4 * NC; i += 128)
        (&warp_hist[0][0])[i] = 0;
    __syncthreads();

    const int p = b * TILE_M + tid;
    const int a = g_assign[s * NPTS + p];

    unsigned mask = __match_any_sync(0xffffffffu, a);
    int lrank  = __popc(mask & ((1u << lane) - 1));
    int leader = __ffs(mask) - 1;
    if (lane == leader) warp_hist[w][a] = __popc(mask);
    __syncthreads();

    int pre = 0;
#pragma unroll
    for (int ww = 0; ww < 4; ww++)
        if (ww < w) pre += warp_hist[ww][a];

    int pos = g_off[s * NC + a]
            + g_bhoff[((size_t)s * NC + a) * NTILE + b]
            + pre + lrank;
    g_bucket[s * NPTS + pos] = (unsigned short)p;
}

// ---------------- update: float4 gather (16 streams x 16 lanes) ----------------
__global__ void update_kernel(const float* __restrict__ x, int cursel,
                              float* __restrict__ outp) {
    __shared__ unsigned short sl[256];
    __shared__ float4 part4[256];
    __shared__ float c2p[2];
    const int s = blockIdx.y, k = blockIdx.x, t = threadIdx.x;  // 256 threads
    const int g = t >> 4, l = t & 15;     // point-stream / float4-lane
    const int base  = s * NC + k;
    const int start = g_off[base];
    const int count = g_cnt[base];

    float4 acc = make_float4(0.f, 0.f, 0.f, 0.f);
    for (int b = 0; b < count; b += 256) {
        int m = min(256, count - b);
        if (t < m) sl[t] = g_bucket[s * NPTS + start + b + t];
        __syncthreads();
        for (int i = g; i < m; i += 16) {
            float4 v = *(const float4*)(x + ((size_t)sl[i] * NS + s) * D + l * 4);
            acc.x += v.x; acc.y += v.y; acc.z += v.z; acc.w += v.w;
        }
        __syncthreads();
    }
    part4[t] = acc;
    __syncthreads();

    if (t < 64) {                         // t = dim
        const int lq = t >> 2, comp = t & 3;
        float sum = 0.f;
#pragma unroll
        for (int gg = 0; gg < 16; gg++) {
            float4 v = part4[gg * 16 + lq];
            sum += (comp == 0) ? v.x : (comp == 1) ? v.y : (comp == 2) ? v.z : v.w;
        }
        size_t idx = (size_t)base * D + t;
        float res = (count > 0) ? (sum / (float)count) : g_c[cursel][idx];
        float* dst = outp ? outp : g_c[1 - cursel];
        dst[idx] = res;
        g_cb[idx] = __float2bfloat16(res);
        float sq = res * res;
#pragma unroll
        for (int o = 16; o > 0; o >>= 1) sq += __shfl_down_sync(0xffffffffu, sq, o);
        if ((t & 31) == 0) c2p[t >> 5] = sq;
    }
    __syncthreads();
    if (t == 0) g_c2[base] = c2p[0] + c2p[1];
}

// ---------------- launch ----------------
extern "C" void kernel_launch(void* const* d_in, const int* in_sizes, int n_in,
                              void* d_out, int out_size) {
    const float* x = (const float*)d_in[0];
    float* out = (float*)d_out;

    cudaFuncSetAttribute(gemm_assign_kernel,
                         cudaFuncAttributeMaxDynamicSharedMemorySize, SM_TOTAL);

    init_c_kernel<<<(NS * NC * D) / 256, 256>>>(x);
    init_xb_kernel<<<(NS * NPTS * D) / 256, 256>>>(x);
    conv_c_kernel<<<dim3(NC, NS), 64>>>(0);

    int cur = 0;
    for (int it = 0; it < NITER; ++it) {
        gemm_assign_kernel<<<dim3(NTILE, NS), 256, SM_TOTAL>>>(x, cur);
        scan_row_kernel<<<dim3(NC / 8, NS), 256>>>();
        scan_off_kernel<<<NS, NC>>>();
        scatter_kernel<<<dim3(NTILE, NS), 128>>>();
        update_kernel<<<dim3(NC, NS), 256>>>(x, cur,
                                             (it == NITER - 1) ? out : nullptr);
        cur ^= 1;
    }
}